// round 10
// baseline (speedup 1.0000x reference)
#include <cuda_runtime.h>

#define H 15
// Padded packed-weight layout (u64 {w,w} each), 16B-aligned for LDC.128:
//  [0,30)    W1 k-major pairs: slot 2k+c = W1[c*H+k] * -log2e
//  [32,47)   b1 * -log2e
//  [48,288)  W2 transposed, 16/row: slot 48+16k+j = W2[j*H+k]  (j<15, pad 0)
//  [288,303) b2 * -log2e
//  [304,544) W3 transposed, 16/row: slot 304+16k+j = W3[j*H+k]
//  [544,559) b3 * -log2e
//  [560,576) W4[j] (pad 0)
//  [576]     b4 * -log2e
#define NWV 290     // ulonglong2 count (580 u64)

typedef unsigned long long u64;

__device__ ulonglong2 g_packed2[NWV];
__constant__ ulonglong2 cw2[NWV];

// ---- packed f32x2 helpers (sm_100+ PTX) ----
__device__ __forceinline__ u64 pk(float a, float b) {
    u64 r; asm("mov.b64 %0,{%1,%2};" : "=l"(r) : "f"(a), "f"(b)); return r;
}
__device__ __forceinline__ void upk(u64 v, float& a, float& b) {
    asm("mov.b64 {%0,%1},%2;" : "=f"(a), "=f"(b) : "l"(v));
}
__device__ __forceinline__ u64 fma2(u64 a, u64 b, u64 c) {
    u64 r; asm("fma.rn.f32x2 %0,%1,%2,%3;" : "=l"(r) : "l"(a), "l"(b), "l"(c)); return r;
}

// t = -log2e * a arrives directly from the pre-scaled GEMV.
// g = t * rcp(1 + ex2(t)) = -log2e * SiLU(a); the compensation folds into the
// next (linear) layer, whose weights therefore stay unscaled.
__device__ __forceinline__ u64 act2(u64 t) {
    float t0, t1; upk(t, t0, t1);
    float e0, e1;
    asm("ex2.approx.f32 %0,%1;" : "=f"(e0) : "f"(t0));
    asm("ex2.approx.f32 %0,%1;" : "=f"(e1) : "f"(t1));
    float d0 = e0 + 1.0f, d1 = e1 + 1.0f;
    float r0, r1;
    asm("rcp.approx.f32 %0,%1;" : "=f"(r0) : "f"(d0));
    asm("rcp.approx.f32 %0,%1;" : "=f"(r1) : "f"(d1));
    return pk(t0 * r0, t1 * r1);
}

// final sigmoid: sigma(a) = rcp(1 + ex2(t)), t = -log2e * a
__device__ __forceinline__ void sig2s(u64 t, float& r0, float& r1) {
    float t0, t1; upk(t, t0, t1);
    float e0, e1;
    asm("ex2.approx.f32 %0,%1;" : "=f"(e0) : "f"(t0));
    asm("ex2.approx.f32 %0,%1;" : "=f"(e1) : "f"(t1));
    float d0 = e0 + 1.0f, d1 = e1 + 1.0f;
    asm("rcp.approx.f32 %0,%1;" : "=f"(r0) : "f"(d0));
    asm("rcp.approx.f32 %0,%1;" : "=f"(r1) : "f"(d1));
}

#define NLOG2E (-1.4426950408889634f)

__global__ void prep_kernel(const float* __restrict__ W1, const float* __restrict__ b1,
                            const float* __restrict__ W2, const float* __restrict__ b2,
                            const float* __restrict__ W3, const float* __restrict__ b3,
                            const float* __restrict__ W4, const float* __restrict__ b4) {
    int i = threadIdx.x;
    if (i >= 2 * NWV) return;
    float v = 0.0f;   // pads stay zero
    if      (i < 30)              { int k = i >> 1, c = i & 1; v = W1[c * H + k] * NLOG2E; }
    else if (i >= 32  && i < 47)  { v = b1[i - 32] * NLOG2E; }
    else if (i >= 48  && i < 288) { int l = i - 48,  k = l >> 4, j = l & 15; if (j < H) v = W2[j * H + k]; }
    else if (i >= 288 && i < 303) { v = b2[i - 288] * NLOG2E; }
    else if (i >= 304 && i < 544) { int l = i - 304, k = l >> 4, j = l & 15; if (j < H) v = W3[j * H + k]; }
    else if (i >= 544 && i < 559) { v = b3[i - 544] * NLOG2E; }
    else if (i >= 560 && i < 575) { v = W4[i - 560]; }
    else if (i == 576)            { v = b4[0] * NLOG2E; }
    u64 p; asm("mov.b64 %0,{%1,%1};" : "=l"(p) : "f"(v));
    ((u64*)g_packed2)[i] = p;
}

// 2 rows per thread, packed f32x2 math, weights in constant memory with
// LDC.128 pair loads (two packed weights per issue slot).
__global__ __launch_bounds__(256) void mlp2_kernel(const float4* __restrict__ x,
                                                   float2* __restrict__ out,
                                                   int npair) {
    const u64* cwu = (const u64*)cw2;

    int i = blockIdx.x * blockDim.x + threadIdx.x;
    if (i >= npair) return;

    float4 xv = x[i];                  // {x0,y0,x1,y1} = rows 2i, 2i+1
    u64 xx = pk(xv.x, xv.z);
    u64 yy = pk(xv.y, xv.w);

    u64 h1[H], h2[H];

    // Layer 1: Linear(2,H)*-log2e -> act  (one LDC.128 per k: {W1_0k, W1_1k})
#pragma unroll
    for (int k = 0; k < H; k++) {
        ulonglong2 w = cw2[k];
        u64 t = fma2(xx, w.x, fma2(yy, w.y, cwu[32 + k]));
        h1[k] = act2(t);
    }

    // Layer 2: Linear(H,H) -> act  (8x LDC.128 per k)
#pragma unroll
    for (int k = 0; k < H; k++) {
        u64 t = cwu[288 + k];
#pragma unroll
        for (int jj = 0; jj < 8; jj++) {
            ulonglong2 w = cw2[(48 + k * 16) / 2 + jj];
            t = fma2(h1[2 * jj], w.x, t);
            if (2 * jj + 1 < H) t = fma2(h1[2 * jj + 1], w.y, t);
        }
        h2[k] = act2(t);
    }

    // Layer 3 (reuse h1)
#pragma unroll
    for (int k = 0; k < H; k++) {
        u64 t = cwu[544 + k];
#pragma unroll
        for (int jj = 0; jj < 8; jj++) {
            ulonglong2 w = cw2[(304 + k * 16) / 2 + jj];
            t = fma2(h2[2 * jj], w.x, t);
            if (2 * jj + 1 < H) t = fma2(h2[2 * jj + 1], w.y, t);
        }
        h1[k] = act2(t);
    }

    // Layer 4 + sigmoid
    u64 t = cwu[576];
#pragma unroll
    for (int jj = 0; jj < 8; jj++) {
        ulonglong2 w = cw2[560 / 2 + jj];
        t = fma2(h1[2 * jj], w.x, t);
        if (2 * jj + 1 < H) t = fma2(h1[2 * jj + 1], w.y, t);
    }

    float s0, s1;
    sig2s(t, s0, s1);
    out[i] = make_float2(s0, s1);
}

extern "C" void kernel_launch(void* const* d_in, const int* in_sizes, int n_in,
                              void* d_out, int out_size) {
    // Inputs: x, W1, b1, W2, b2, W3, b3, W4, b4
    const float* x = (const float*)d_in[0];

    prep_kernel<<<1, 608>>>((const float*)d_in[1], (const float*)d_in[2],
                            (const float*)d_in[3], (const float*)d_in[4],
                            (const float*)d_in[5], (const float*)d_in[6],
                            (const float*)d_in[7], (const float*)d_in[8]);

    void* src = nullptr;
    cudaGetSymbolAddress(&src, g_packed2);  // host-side query, capture-safe
    cudaMemcpyToSymbolAsync(cw2, src, NWV * sizeof(ulonglong2), 0,
                            cudaMemcpyDeviceToDevice, 0);

    int n = in_sizes[0] / 2;   // rows
    int npair = n / 2;         // 2 rows per thread
    int threads = 256;
    int blocks = (npair + threads - 1) / threads;
    mlp2_kernel<<<blocks, threads>>>((const float4*)x, (float2*)d_out, npair);
}

// round 12
// speedup vs baseline: 1.6873x; 1.6873x over previous
#include <cuda_runtime.h>

#define H 15
#define NPACK 541
// packed-weight layout (u64 {w,w} per weight), t-space scaling folded in:
// W1,b1 scaled by -log2(e); W2,W3,W4 unscaled; b2,b3,b4 scaled by -log2(e).
#define OW1 0      // 30
#define OB1 30     // 15
#define OW2 45     // 225
#define OB2 270    // 15
#define OW3 285    // 225
#define OB3 510    // 15
#define OW4 525    // 15
#define OB4 540    // 1

typedef unsigned long long u64;

__device__ u64 g_packed[NPACK];
__constant__ u64 cw[NPACK];

// ---- packed f32x2 helpers (sm_100+ PTX) ----
__device__ __forceinline__ u64 pk(float a, float b) {
    u64 r; asm("mov.b64 %0,{%1,%2};" : "=l"(r) : "f"(a), "f"(b)); return r;
}
__device__ __forceinline__ void upk(u64 v, float& a, float& b) {
    asm("mov.b64 {%0,%1},%2;" : "=f"(a), "=f"(b) : "l"(v));
}
__device__ __forceinline__ u64 fma2(u64 a, u64 b, u64 c) {
    u64 r; asm("fma.rn.f32x2 %0,%1,%2,%3;" : "=l"(r) : "l"(a), "l"(b), "l"(c)); return r;
}
__device__ __forceinline__ u64 mul2(u64 a, u64 b) {
    u64 r; asm("mul.rn.f32x2 %0,%1,%2;" : "=l"(r) : "l"(a), "l"(b)); return r;
}

// t = -log2e * a arrives directly from the pre-scaled GEMV.
// g = t * rcp(1 + ex2(t)) = -log2e * SiLU(a); the compensation folds into the
// next (linear) layer, whose weights therefore stay unscaled.
__device__ __forceinline__ u64 act2(u64 t) {
    float t0, t1; upk(t, t0, t1);
    float e0, e1;
    asm("ex2.approx.f32 %0,%1;" : "=f"(e0) : "f"(t0));
    asm("ex2.approx.f32 %0,%1;" : "=f"(e1) : "f"(t1));
    float d0 = e0 + 1.0f, d1 = e1 + 1.0f;
    float r0, r1;
    asm("rcp.approx.f32 %0,%1;" : "=f"(r0) : "f"(d0));
    asm("rcp.approx.f32 %0,%1;" : "=f"(r1) : "f"(d1));
    return mul2(t, pk(r0, r1));     // packed SiLU mul: 1 slot instead of 2
}

// final sigmoid: sigma(a) = rcp(1 + ex2(t)), t = -log2e * a
__device__ __forceinline__ void sig2s(u64 t, float& r0, float& r1) {
    float t0, t1; upk(t, t0, t1);
    float e0, e1;
    asm("ex2.approx.f32 %0,%1;" : "=f"(e0) : "f"(t0));
    asm("ex2.approx.f32 %0,%1;" : "=f"(e1) : "f"(t1));
    float d0 = e0 + 1.0f, d1 = e1 + 1.0f;
    asm("rcp.approx.f32 %0,%1;" : "=f"(r0) : "f"(d0));
    asm("rcp.approx.f32 %0,%1;" : "=f"(r1) : "f"(d1));
}

#define NLOG2E (-1.4426950408889634f)

// Duplicate each scalar weight into a {w',w'} u64 pair with t-space scaling.
__global__ void prep_kernel(const float* __restrict__ W1, const float* __restrict__ b1,
                            const float* __restrict__ W2, const float* __restrict__ b2,
                            const float* __restrict__ W3, const float* __restrict__ b3,
                            const float* __restrict__ W4, const float* __restrict__ b4) {
    int i = threadIdx.x;
    float v;
    if      (i < OB1) v = W1[i - OW1] * NLOG2E;   // W1 scaled
    else if (i < OW2) v = b1[i - OB1] * NLOG2E;   // b1 scaled
    else if (i < OB2) v = W2[i - OW2];            // W2 unscaled
    else if (i < OW3) v = b2[i - OB2] * NLOG2E;   // b2 scaled
    else if (i < OB3) v = W3[i - OW3];            // W3 unscaled
    else if (i < OW4) v = b3[i - OB3] * NLOG2E;   // b3 scaled
    else if (i < OB4) v = W4[i - OW4];            // W4 unscaled
    else if (i == OB4) v = b4[0] * NLOG2E;        // b4 scaled
    else return;
    u64 p; asm("mov.b64 %0,{%1,%1};" : "=l"(p) : "f"(v));
    g_packed[i] = p;
}

// 2 rows per thread, packed f32x2 math, weights as LDC.64 from constant mem.
// 128-thread blocks: 7 resident blocks @71 regs -> 28 warps/SM (vs 24 at 256).
__global__ __launch_bounds__(128) void mlp2_kernel(const float4* __restrict__ x,
                                                   float2* __restrict__ out,
                                                   int npair) {
    int i = blockIdx.x * blockDim.x + threadIdx.x;
    if (i >= npair) return;

    float4 xv = x[i];                  // {x0,y0,x1,y1} = rows 2i, 2i+1
    u64 xx = pk(xv.x, xv.z);
    u64 yy = pk(xv.y, xv.w);

    u64 h1[H], h2[H];

    // Layer 1: Linear(2,H)*-log2e -> act
#pragma unroll
    for (int k = 0; k < H; k++) {
        u64 t = fma2(xx, cw[OW1 + k], fma2(yy, cw[OW1 + H + k], cw[OB1 + k]));
        h1[k] = act2(t);
    }

    // Layer 2: Linear(H,H) -> act
#pragma unroll
    for (int k = 0; k < H; k++) {
        u64 t = cw[OB2 + k];
#pragma unroll
        for (int j = 0; j < H; j++) t = fma2(h1[j], cw[OW2 + j * H + k], t);
        h2[k] = act2(t);
    }

    // Layer 3 (reuse h1)
#pragma unroll
    for (int k = 0; k < H; k++) {
        u64 t = cw[OB3 + k];
#pragma unroll
        for (int j = 0; j < H; j++) t = fma2(h2[j], cw[OW3 + j * H + k], t);
        h1[k] = act2(t);
    }

    // Layer 4 + sigmoid
    u64 t = cw[OB4];
#pragma unroll
    for (int j = 0; j < H; j++) t = fma2(h1[j], cw[OW4 + j], t);

    float s0, s1;
    sig2s(t, s0, s1);
    out[i] = make_float2(s0, s1);
}

extern "C" void kernel_launch(void* const* d_in, const int* in_sizes, int n_in,
                              void* d_out, int out_size) {
    // Inputs: x, W1, b1, W2, b2, W3, b3, W4, b4
    const float* x = (const float*)d_in[0];

    prep_kernel<<<1, 544>>>((const float*)d_in[1], (const float*)d_in[2],
                            (const float*)d_in[3], (const float*)d_in[4],
                            (const float*)d_in[5], (const float*)d_in[6],
                            (const float*)d_in[7], (const float*)d_in[8]);

    void* src = nullptr;
    cudaGetSymbolAddress(&src, g_packed);  // host-side query, capture-safe
    cudaMemcpyToSymbolAsync(cw, src, NPACK * sizeof(u64), 0,
                            cudaMemcpyDeviceToDevice, 0);

    int n = in_sizes[0] / 2;   // rows
    int npair = n / 2;         // 2 rows per thread
    int threads = 128;
    int blocks = (npair + threads - 1) / threads;
    mlp2_kernel<<<blocks, threads>>>((const float4*)x, (float2*)d_out, npair);
}